// round 2
// baseline (speedup 1.0000x reference)
#include <cuda_runtime.h>

// Problem constants (fixed instance: MultiHeadAggregator_55825984913801)
#define L_    12     // layers used (hidden_states[1:])
#define B_    8
#define T_    2048
#define H_    768
#define C_    4
#define MAXNT 160    // max masked positions we support (expected ~12, hte <= 5)

// Scratch for mask index lists: [maskType][batch][slot]
__device__ int g_mask_idx[2][B_][MAXNT];
__device__ int g_mask_cnt[2][B_];

// ---------------------------------------------------------------------------
// Kernel 1: per batch row, find (a) first occurrence of hte_token_id (window
// mask start), (b) the compact list of desc-token positions.
// Integer width (int32 vs int64) of input_ids / d_token_ids is detected on
// device: tokens are small non-negative values, so an int64 buffer viewed as
// int32 has all odd words == 0.
// ---------------------------------------------------------------------------
__global__ void find_masks_kernel(const int* __restrict__ ids32,
                                  const int* __restrict__ hte_ptr,   // low 4B of scalar
                                  const int* __restrict__ win_ptr,   // low 4B of scalar
                                  const int* __restrict__ dtok32,
                                  int n_d) {
    int b = blockIdx.x;
    __shared__ int s_min;
    __shared__ int s_cnt;
    __shared__ int s_stride;   // 1 if int32 data, 2 if int64 data
    if (threadIdx.x == 0) {
        s_min = 0x7fffffff; s_cnt = 0;
        // dtype probe over first 256 words of the buffer (row 0)
        bool odd_zero = true;
        #pragma unroll 4
        for (int i = 1; i < 256; i += 2) odd_zero &= (ids32[i] == 0);
        s_stride = odd_zero ? 2 : 1;
    }
    __syncthreads();

    const int st  = s_stride;
    const int hte = *hte_ptr;
    const int* row = ids32 + (size_t)b * T_ * st;

    int d0 = (n_d > 0) ? dtok32[0 * st] : 0x7fffffff;
    int d1 = (n_d > 1) ? dtok32[1 * st] : 0x7fffffff;
    int d2 = (n_d > 2) ? dtok32[2 * st] : 0x7fffffff;

    for (int t = threadIdx.x; t < T_; t += blockDim.x) {
        int id = row[(size_t)t * st];
        if (id == hte) atomicMin(&s_min, t);
        bool isd = (id == d0) | (id == d1) | (id == d2);
        // generic fallback for n_d > 3 (not expected here)
        for (int k = 3; k < n_d; k++) isd |= (id == dtok32[k * st]);
        if (isd) {
            int p = atomicAdd(&s_cnt, 1);
            if (p < MAXNT) g_mask_idx[1][b][p] = t;   // order irrelevant (softmax is permutation-invariant)
        }
    }
    __syncthreads();

    if (threadIdx.x == 0) {
        // hte window mask: [pos, min(pos+window, T-1)]; pos = T-1 if absent
        int pos = (s_min == 0x7fffffff) ? (T_ - 1) : s_min;
        int hi  = pos + (*win_ptr);
        if (hi > T_ - 1) hi = T_ - 1;
        int cnt = hi - pos + 1;
        if (cnt > MAXNT) cnt = MAXNT;
        g_mask_cnt[0][b] = cnt;
        for (int i = 0; i < cnt; i++) g_mask_idx[0][b][i] = pos + i;

        // desc mask: fallback to {0} if no desc token present
        int dc = s_cnt;
        if (dc == 0) { g_mask_idx[1][b][0] = 0; dc = 1; }
        if (dc > MAXNT) dc = MAXNT;
        g_mask_cnt[1][b] = dc;
    }
}

// ---------------------------------------------------------------------------
// Kernel 2: one block per (batch, maskType). Computes masked attention pooling
// over ONLY the masked positions (non-masked contribute exactly 0 after the
// -1e30 masking + fp32 softmax: exp(-1e30 - max) underflows to 0).
// ---------------------------------------------------------------------------
__global__ __launch_bounds__(256)
void pool_kernel(const float* __restrict__ hidden,        // (L_+1, B, T, H)
                 const float* __restrict__ layer_logits,  // (L_)
                 const float* __restrict__ scorer_w,      // (C, H)
                 float* __restrict__ out) {               // (B, 2, C, H)
    const int b   = blockIdx.x >> 1;
    const int mt  = blockIdx.x & 1;
    const int tid = threadIdx.x;
    const int NTH = 256;

    __shared__ float s_sc[C_ * H_];          // 12 KB
    __shared__ float s_w[L_][MAXNT][C_];     // 30 KB : scores -> attn*layer_w
    __shared__ float s_lw[L_];
    __shared__ int   s_idx[MAXNT];

    const int nt = g_mask_cnt[mt][b];
    for (int i = tid; i < nt; i += NTH)        s_idx[i] = g_mask_idx[mt][b][i];
    for (int i = tid; i < C_ * H_; i += NTH)   s_sc[i]  = scorer_w[i];
    if (tid == 0) {
        // layer softmax (12 elems, serial)
        float m = -1e30f;
        #pragma unroll
        for (int l = 0; l < L_; l++) m = fmaxf(m, layer_logits[l]);
        float s = 0.f;
        #pragma unroll
        for (int l = 0; l < L_; l++) { float e = expf(layer_logits[l] - m); s_lw[l] = e; s += e; }
        float inv = 1.f / s;
        #pragma unroll
        for (int l = 0; l < L_; l++) s_lw[l] *= inv;
    }
    __syncthreads();

    // ---- Step 1: scores[l][ti][c] = <hidden[l+1,b,t,:], scorer_w[c,:]> -----
    // warp-per-(l,ti) pair; 4 accumulators (C=4) per lane, warp-reduce.
    {
        const int wid = tid >> 5, lane = tid & 31;
        const int npairs = L_ * nt;
        for (int p = wid; p < npairs; p += (NTH >> 5)) {
            const int l = p / nt, ti = p % nt;
            const float* hp = hidden + (((size_t)(l + 1) * B_ + b) * T_ + s_idx[ti]) * H_;
            float a0 = 0.f, a1 = 0.f, a2 = 0.f, a3 = 0.f;
            for (int h = lane; h < H_; h += 32) {
                float x = hp[h];
                a0 = fmaf(x, s_sc[0 * H_ + h], a0);
                a1 = fmaf(x, s_sc[1 * H_ + h], a1);
                a2 = fmaf(x, s_sc[2 * H_ + h], a2);
                a3 = fmaf(x, s_sc[3 * H_ + h], a3);
            }
            #pragma unroll
            for (int o = 16; o; o >>= 1) {
                a0 += __shfl_xor_sync(0xffffffffu, a0, o);
                a1 += __shfl_xor_sync(0xffffffffu, a1, o);
                a2 += __shfl_xor_sync(0xffffffffu, a2, o);
                a3 += __shfl_xor_sync(0xffffffffu, a3, o);
            }
            if (lane == 0) {
                s_w[l][ti][0] = a0; s_w[l][ti][1] = a1;
                s_w[l][ti][2] = a2; s_w[l][ti][3] = a3;
            }
        }
    }
    __syncthreads();

    // ---- Step 2: softmax over masked positions, fold in layer weight -------
    if (tid < L_ * C_) {
        const int l = tid / C_, c = tid % C_;
        float m = -1e30f;
        for (int i = 0; i < nt; i++) m = fmaxf(m, s_w[l][i][c]);
        float s = 0.f;
        for (int i = 0; i < nt; i++) { float e = expf(s_w[l][i][c] - m); s_w[l][i][c] = e; s += e; }
        float inv = s_lw[l] / s;
        for (int i = 0; i < nt; i++) s_w[l][i][c] *= inv;
    }
    __syncthreads();

    // ---- Step 3: out[c][h] = sum_l sum_ti w[l][ti][c] * hidden[l+1,b,t,h] --
    // thread-per-h: coalesced reads of the (few) masked hidden rows (L2-hot).
    float* op = out + ((size_t)b * 2 + mt) * (C_ * H_);
    for (int h = tid; h < H_; h += NTH) {
        float a0 = 0.f, a1 = 0.f, a2 = 0.f, a3 = 0.f;
        #pragma unroll
        for (int l = 0; l < L_; l++) {
            const float* hb = hidden + ((size_t)(l + 1) * B_ + b) * (size_t)T_ * H_;
            for (int i = 0; i < nt; i++) {
                float x = hb[(size_t)s_idx[i] * H_ + h];
                a0 = fmaf(s_w[l][i][0], x, a0);
                a1 = fmaf(s_w[l][i][1], x, a1);
                a2 = fmaf(s_w[l][i][2], x, a2);
                a3 = fmaf(s_w[l][i][3], x, a3);
            }
        }
        op[0 * H_ + h] = a0;
        op[1 * H_ + h] = a1;
        op[2 * H_ + h] = a2;
        op[3 * H_ + h] = a3;
    }
}

// ---------------------------------------------------------------------------
// Launch. Inputs (metadata order):
//  0 hidden_states f32 (13,8,2048,768)   1 input_ids int (8,2048)
//  2 layer_logits f32 (12)               3 scorer_w  f32 (4,768)
//  4 hte_token_id scalar int             5 d_token_ids int (3)
//  6 window scalar int
// Output: f32 (8, 6144)
// ---------------------------------------------------------------------------
extern "C" void kernel_launch(void* const* d_in, const int* in_sizes, int n_in,
                              void* d_out, int out_size) {
    const float* hidden = (const float*)d_in[0];
    const int*   ids    = (const int*)d_in[1];
    const float* logits = (const float*)d_in[2];
    const float* scorer = (const float*)d_in[3];
    const int*   hte    = (const int*)d_in[4];   // low 4B valid for i32/i64 small values
    const int*   dtok   = (const int*)d_in[5];
    const int*   win    = (const int*)d_in[6];
    const int n_d = in_sizes[5];

    find_masks_kernel<<<B_, 256>>>(ids, hte, win, dtok, n_d);
    pool_kernel<<<2 * B_, 256>>>(hidden, logits, scorer, (float*)d_out);
}

// round 3
// speedup vs baseline: 2.3420x; 2.3420x over previous
#include <cuda_runtime.h>

// Problem constants (fixed instance: MultiHeadAggregator_55825984913801)
#define L_    12     // layers used (hidden_states[1:])
#define B_    8
#define T_    2048
#define H_    768
#define C_    4
#define MAXNT 160    // max masked positions supported (expected: hte<=5, desc~12)

// Scratch: mask index lists, counts, layer softmax, final attention weights
__device__ int   g_mask_idx[2][B_][MAXNT];
__device__ int   g_mask_cnt[2][B_];
__device__ float g_lw[L_];
__device__ float g_w[2][B_][L_][MAXNT][C_];   // attn * layer_w  (~491 KB)

// ---------------------------------------------------------------------------
// Kernel 1: per batch row, find first hte position + compact desc positions.
// Block 0 thread 0 also computes the layer softmax.
// int32 vs int64 input_ids detected on device (int64 little-endian view of
// small tokens has every odd 32-bit word == 0).
// ---------------------------------------------------------------------------
__global__ void find_masks_kernel(const int* __restrict__ ids32,
                                  const int* __restrict__ hte_ptr,
                                  const int* __restrict__ win_ptr,
                                  const int* __restrict__ dtok32,
                                  int n_d,
                                  const float* __restrict__ layer_logits) {
    int b = blockIdx.x;
    __shared__ int s_min, s_cnt, s_stride;
    if (threadIdx.x == 0) {
        s_min = 0x7fffffff; s_cnt = 0;
        bool odd_zero = true;
        #pragma unroll 4
        for (int i = 1; i < 256; i += 2) odd_zero &= (ids32[i] == 0);
        s_stride = odd_zero ? 2 : 1;
    }
    if (b == 0 && threadIdx.x == 32) {   // layer softmax, one thread
        float m = -1e30f;
        #pragma unroll
        for (int l = 0; l < L_; l++) m = fmaxf(m, layer_logits[l]);
        float s = 0.f, e[L_];
        #pragma unroll
        for (int l = 0; l < L_; l++) { e[l] = expf(layer_logits[l] - m); s += e[l]; }
        float inv = 1.f / s;
        #pragma unroll
        for (int l = 0; l < L_; l++) g_lw[l] = e[l] * inv;
    }
    __syncthreads();

    const int st  = s_stride;
    const int hte = *hte_ptr;
    const int* row = ids32 + (size_t)b * T_ * st;

    int d0 = (n_d > 0) ? dtok32[0 * st] : 0x7fffffff;
    int d1 = (n_d > 1) ? dtok32[1 * st] : 0x7fffffff;
    int d2 = (n_d > 2) ? dtok32[2 * st] : 0x7fffffff;

    for (int t = threadIdx.x; t < T_; t += blockDim.x) {
        int id = row[(size_t)t * st];
        if (id == hte) atomicMin(&s_min, t);
        bool isd = (id == d0) | (id == d1) | (id == d2);
        for (int k = 3; k < n_d; k++) isd |= (id == dtok32[k * st]);
        if (isd) {
            int p = atomicAdd(&s_cnt, 1);
            if (p < MAXNT) g_mask_idx[1][b][p] = t;  // order irrelevant (softmax permutation-invariant)
        }
    }
    __syncthreads();

    if (threadIdx.x == 0) {
        int pos = (s_min == 0x7fffffff) ? (T_ - 1) : s_min;
        int hi  = pos + (*win_ptr);
        if (hi > T_ - 1) hi = T_ - 1;
        int cnt = hi - pos + 1;
        if (cnt > MAXNT) cnt = MAXNT;
        g_mask_cnt[0][b] = cnt;
        for (int i = 0; i < cnt; i++) g_mask_idx[0][b][i] = pos + i;

        int dc = s_cnt;
        if (dc == 0) { g_mask_idx[1][b][0] = 0; dc = 1; }
        if (dc > MAXNT) dc = MAXNT;
        g_mask_cnt[1][b] = dc;
    }
}

// ---------------------------------------------------------------------------
// Kernel 2: one block per (b, mt, l). Gathers its masked rows (float4 loads),
// computes scores[ti][c], softmax over ti, folds in layer weight, writes g_w.
// Only masked positions contribute: -1e30 masking + fp32 softmax makes all
// other positions exactly 0.
// ---------------------------------------------------------------------------
__global__ __launch_bounds__(256)
void scores_kernel(const float* __restrict__ hidden,     // (L_+1, B, T, H)
                   const float* __restrict__ scorer_w) { // (C, H)
    const int l  = blockIdx.x;          // 0..L_-1
    const int bm = blockIdx.y;          // 0..2*B_-1
    const int b  = bm >> 1;
    const int mt = bm & 1;
    const int tid = threadIdx.x;
    const int wid = tid >> 5, lane = tid & 31;

    __shared__ float4 s_sc4[C_ * (H_ / 4)];   // 12 KB scorer
    __shared__ float  s_s[MAXNT][C_];         // scores
    __shared__ int    s_idx[MAXNT];

    const int nt = g_mask_cnt[mt][b];
    for (int i = tid; i < nt; i += 256) s_idx[i] = g_mask_idx[mt][b][i];
    {
        const float4* sw4 = (const float4*)scorer_w;
        for (int i = tid; i < C_ * (H_ / 4); i += 256) s_sc4[i] = sw4[i];
    }
    __syncthreads();

    const float lw = g_lw[l];
    const float4* hbase = (const float4*)(hidden + (((size_t)(l + 1) * B_ + b) * T_) * H_);

    for (int ti = wid; ti < nt; ti += 8) {
        const float4* hp = hbase + (size_t)s_idx[ti] * (H_ / 4);
        float a0 = 0.f, a1 = 0.f, a2 = 0.f, a3 = 0.f;
        #pragma unroll
        for (int j = 0; j < H_ / 4 / 32; j++) {         // 6 iterations
            int idx = j * 32 + lane;
            float4 x  = hp[idx];
            float4 w0 = s_sc4[0 * (H_ / 4) + idx];
            float4 w1 = s_sc4[1 * (H_ / 4) + idx];
            float4 w2 = s_sc4[2 * (H_ / 4) + idx];
            float4 w3 = s_sc4[3 * (H_ / 4) + idx];
            a0 = fmaf(x.x, w0.x, fmaf(x.y, w0.y, fmaf(x.z, w0.z, fmaf(x.w, w0.w, a0))));
            a1 = fmaf(x.x, w1.x, fmaf(x.y, w1.y, fmaf(x.z, w1.z, fmaf(x.w, w1.w, a1))));
            a2 = fmaf(x.x, w2.x, fmaf(x.y, w2.y, fmaf(x.z, w2.z, fmaf(x.w, w2.w, a2))));
            a3 = fmaf(x.x, w3.x, fmaf(x.y, w3.y, fmaf(x.z, w3.z, fmaf(x.w, w3.w, a3))));
        }
        #pragma unroll
        for (int o = 16; o; o >>= 1) {
            a0 += __shfl_xor_sync(0xffffffffu, a0, o);
            a1 += __shfl_xor_sync(0xffffffffu, a1, o);
            a2 += __shfl_xor_sync(0xffffffffu, a2, o);
            a3 += __shfl_xor_sync(0xffffffffu, a3, o);
        }
        if (lane == 0) {
            s_s[ti][0] = a0; s_s[ti][1] = a1; s_s[ti][2] = a2; s_s[ti][3] = a3;
        }
    }
    __syncthreads();

    // softmax over nt per channel c, scaled by layer weight
    if (tid < C_) {
        const int c = tid;
        float m = -1e30f;
        for (int i = 0; i < nt; i++) m = fmaxf(m, s_s[i][c]);
        float s = 0.f;
        for (int i = 0; i < nt; i++) { float e = expf(s_s[i][c] - m); s_s[i][c] = e; s += e; }
        float inv = lw / s;
        for (int i = 0; i < nt; i++) s_s[i][c] *= inv;
    }
    __syncthreads();

    for (int i = tid; i < nt * C_; i += 256)
        g_w[mt][b][l][i / C_][i % C_] = s_s[i / C_][i % C_];
}

// ---------------------------------------------------------------------------
// Kernel 3: grid (6, 2*B_) x 128 threads; thread-per-h gather-accumulate.
// Rows are L2-resident (kernel 2 just read them).
// ---------------------------------------------------------------------------
__global__ __launch_bounds__(128)
void output_kernel(const float* __restrict__ hidden,
                   float* __restrict__ out) {           // (B, 2, C, H)
    const int seg = blockIdx.x;         // 0..5
    const int bm  = blockIdx.y;         // 0..15
    const int b   = bm >> 1;
    const int mt  = bm & 1;
    const int tid = threadIdx.x;
    const int h   = seg * 128 + tid;

    __shared__ float s_w[L_][MAXNT][C_] ;  // only first nt used
    __shared__ int   s_idx[MAXNT];

    const int nt = g_mask_cnt[mt][b];
    for (int i = tid; i < nt; i += 128) s_idx[i] = g_mask_idx[mt][b][i];
    for (int i = tid; i < L_ * nt * C_; i += 128) {
        int l = i / (nt * C_), r = i % (nt * C_);
        s_w[l][r / C_][r % C_] = g_w[mt][b][l][r / C_][r % C_];
    }
    __syncthreads();

    float a0 = 0.f, a1 = 0.f, a2 = 0.f, a3 = 0.f;
    #pragma unroll
    for (int l = 0; l < L_; l++) {
        const float* hb = hidden + ((size_t)(l + 1) * B_ + b) * (size_t)T_ * H_ + h;
        for (int i = 0; i < nt; i++) {
            float x = hb[(size_t)s_idx[i] * H_];
            a0 = fmaf(s_w[l][i][0], x, a0);
            a1 = fmaf(s_w[l][i][1], x, a1);
            a2 = fmaf(s_w[l][i][2], x, a2);
            a3 = fmaf(s_w[l][i][3], x, a3);
        }
    }
    float* op = out + ((size_t)b * 2 + mt) * (C_ * H_);
    op[0 * H_ + h] = a0;
    op[1 * H_ + h] = a1;
    op[2 * H_ + h] = a2;
    op[3 * H_ + h] = a3;
}

// ---------------------------------------------------------------------------
extern "C" void kernel_launch(void* const* d_in, const int* in_sizes, int n_in,
                              void* d_out, int out_size) {
    const float* hidden = (const float*)d_in[0];
    const int*   ids    = (const int*)d_in[1];
    const float* logits = (const float*)d_in[2];
    const float* scorer = (const float*)d_in[3];
    const int*   hte    = (const int*)d_in[4];   // low 4B valid for i32/i64 small values
    const int*   dtok   = (const int*)d_in[5];
    const int*   win    = (const int*)d_in[6];
    const int n_d = in_sizes[5];

    find_masks_kernel<<<B_, 256>>>(ids, hte, win, dtok, n_d, logits);
    dim3 g2(L_, 2 * B_);
    scores_kernel<<<g2, 256>>>(hidden, scorer);
    dim3 g3(H_ / 128, 2 * B_);
    output_kernel<<<g3, 128>>>(hidden, (float*)d_out);
}

// round 4
// speedup vs baseline: 2.9955x; 1.2790x over previous
#include <cuda_runtime.h>

// Problem constants (fixed instance: MultiHeadAggregator_55825984913801)
#define L_    12     // layers used (hidden_states[1:])
#define B_    8
#define T_    2048
#define H_    768
#define C_    4
#define MAXNT 160    // max masked positions supported (expected: hte<=5, desc~12)
#define TPB   256
#define TOKS_PER_THR (T_ / TPB)   // 8

// Scratch shared between the two kernels
__device__ int   g_mask_idx[2][B_][MAXNT];
__device__ int   g_mask_cnt[2][B_];
__device__ float g_w[2][B_][L_][MAXNT][C_];   // attn * layer_w

// ---------------------------------------------------------------------------
// Kernel 1 (fused masks + scores + softmax): one block per (b, mt, l).
//  - detects int32 vs int64 ids on device (int64 LE view of small tokens has
//    every odd 32-bit word == 0)
//  - recomputes the mask for (b, mt) DETERMINISTICALLY (order-preserving
//    scan compaction) so every block with the same (b,mt) agrees bit-for-bit
//  - gathers masked rows (float4), computes scores, softmax over positions,
//    folds in the layer-softmax weight, writes g_w
// Only masked positions contribute: -1e30 masking + fp32 softmax makes all
// other positions exactly 0, so the dense reference reduces to this sparse form.
// ---------------------------------------------------------------------------
__global__ __launch_bounds__(TPB)
void scores_kernel(const float* __restrict__ hidden,      // (L_+1, B, T, H)
                   const float* __restrict__ scorer_w,    // (C, H)
                   const float* __restrict__ layer_logits,// (L_)
                   const int*   __restrict__ ids32,
                   const int*   __restrict__ hte_ptr,     // low 4B of scalar
                   const int*   __restrict__ win_ptr,     // low 4B of scalar
                   const int*   __restrict__ dtok32,
                   int n_d) {
    const int l  = blockIdx.x;          // 0..L_-1
    const int bm = blockIdx.y;          // 0..2*B_-1
    const int b  = bm >> 1;
    const int mt = bm & 1;
    const int tid  = threadIdx.x;
    const int wid  = tid >> 5, lane = tid & 31;

    __shared__ float4 s_sc4[C_ * (H_ / 4)];   // 12 KB scorer
    __shared__ float  s_s[MAXNT][C_];
    __shared__ int    s_idx[MAXNT];
    __shared__ int    s_nt;
    __shared__ int    s_notzero, s_min;
    __shared__ int    s_wsum[TPB / 32], s_woff[TPB / 32];
    __shared__ float  s_lw;

    // ---- scorer weights to smem (overlaps with the ids scan below) --------
    {
        const float4* sw4 = (const float4*)scorer_w;
        for (int i = tid; i < C_ * (H_ / 4); i += TPB) s_sc4[i] = sw4[i];
    }

    // ---- dtype probe (parallel) -------------------------------------------
    if (tid == 0) { s_notzero = 0; s_min = 0x7fffffff; }
    __syncthreads();
    if (tid < 128 && ids32[2 * tid + 1] != 0) atomicOr(&s_notzero, 1);
    if (tid == 0) {   // layer softmax (12 elems, serial, cheap)
        float m = -1e30f;
        #pragma unroll
        for (int k = 0; k < L_; k++) m = fmaxf(m, layer_logits[k]);
        float s = 0.f, el = 0.f;
        #pragma unroll
        for (int k = 0; k < L_; k++) {
            float e = expf(layer_logits[k] - m);
            s += e;
            if (k == l) el = e;
        }
        s_lw = el / s;
    }
    __syncthreads();
    const int st  = s_notzero ? 1 : 2;
    const int hte = *hte_ptr;
    const int* row = ids32 + (size_t)b * T_ * st;

    // ---- build mask index list for (b, mt), deterministic ------------------
    if (mt == 0) {
        // window mask: first hte position (min-reduce), then [pos, pos+win]
        int local = 0x7fffffff;
        #pragma unroll
        for (int j = 0; j < TOKS_PER_THR; j++) {
            int t = tid * TOKS_PER_THR + j;
            if (row[(size_t)t * st] == hte) local = min(local, t);
        }
        if (local != 0x7fffffff) atomicMin(&s_min, local);
        __syncthreads();
        if (tid == 0) {
            int pos = (s_min == 0x7fffffff) ? (T_ - 1) : s_min;
            int hi  = pos + (*win_ptr);
            if (hi > T_ - 1) hi = T_ - 1;
            int cnt = hi - pos + 1;
            if (cnt > MAXNT) cnt = MAXNT;
            s_nt = cnt;
            for (int i = 0; i < cnt; i++) s_idx[i] = pos + i;
        }
        __syncthreads();
    } else {
        // desc mask: order-preserving compaction (8 consecutive tokens/thread)
        int d0 = (n_d > 0) ? dtok32[0 * st] : 0x7fffffff;
        int d1 = (n_d > 1) ? dtok32[1 * st] : 0x7fffffff;
        int d2 = (n_d > 2) ? dtok32[2 * st] : 0x7fffffff;
        int cnt = 0, loc[TOKS_PER_THR];
        #pragma unroll
        for (int j = 0; j < TOKS_PER_THR; j++) {
            int t  = tid * TOKS_PER_THR + j;
            int id = row[(size_t)t * st];
            bool isd = (id == d0) | (id == d1) | (id == d2);
            for (int k = 3; k < n_d; k++) isd |= (id == dtok32[k * st]);
            if (isd) loc[cnt++] = t;
        }
        // block exclusive scan of cnt
        int inc = cnt;
        #pragma unroll
        for (int o = 1; o < 32; o <<= 1) {
            int y = __shfl_up_sync(0xffffffffu, inc, o);
            if (lane >= o) inc += y;
        }
        if (lane == 31) s_wsum[wid] = inc;
        __syncthreads();
        if (tid == 0) {
            int acc = 0;
            #pragma unroll
            for (int w = 0; w < TPB / 32; w++) { s_woff[w] = acc; acc += s_wsum[w]; }
            int total = acc;
            if (total == 0) { s_idx[0] = 0; total = 1; }
            s_nt = (total > MAXNT) ? MAXNT : total;
        }
        __syncthreads();
        int off = s_woff[wid] + inc - cnt;   // exclusive prefix
        for (int k = 0; k < cnt; k++)
            if (off + k < MAXNT) s_idx[off + k] = loc[k];
        __syncthreads();
    }
    const int nt = s_nt;

    // publish masks for kernel 2 (all (b,mt,l) blocks agree; l==0 writes)
    if (l == 0) {
        if (tid == 0) g_mask_cnt[mt][b] = nt;
        for (int i = tid; i < nt; i += TPB) g_mask_idx[mt][b][i] = s_idx[i];
    }

    // ---- scores: warp per masked position, float4 gathers ------------------
    const float4* hbase = (const float4*)(hidden + (((size_t)(l + 1) * B_ + b) * T_) * H_);
    for (int ti = wid; ti < nt; ti += TPB / 32) {
        const float4* hp = hbase + (size_t)s_idx[ti] * (H_ / 4);
        float a0 = 0.f, a1 = 0.f, a2 = 0.f, a3 = 0.f;
        #pragma unroll
        for (int j = 0; j < H_ / 4 / 32; j++) {        // 6 iterations
            int idx = j * 32 + lane;
            float4 x  = hp[idx];
            float4 w0 = s_sc4[0 * (H_ / 4) + idx];
            float4 w1 = s_sc4[1 * (H_ / 4) + idx];
            float4 w2 = s_sc4[2 * (H_ / 4) + idx];
            float4 w3 = s_sc4[3 * (H_ / 4) + idx];
            a0 = fmaf(x.x, w0.x, fmaf(x.y, w0.y, fmaf(x.z, w0.z, fmaf(x.w, w0.w, a0))));
            a1 = fmaf(x.x, w1.x, fmaf(x.y, w1.y, fmaf(x.z, w1.z, fmaf(x.w, w1.w, a1))));
            a2 = fmaf(x.x, w2.x, fmaf(x.y, w2.y, fmaf(x.z, w2.z, fmaf(x.w, w2.w, a2))));
            a3 = fmaf(x.x, w3.x, fmaf(x.y, w3.y, fmaf(x.z, w3.z, fmaf(x.w, w3.w, a3))));
        }
        #pragma unroll
        for (int o = 16; o; o >>= 1) {
            a0 += __shfl_xor_sync(0xffffffffu, a0, o);
            a1 += __shfl_xor_sync(0xffffffffu, a1, o);
            a2 += __shfl_xor_sync(0xffffffffu, a2, o);
            a3 += __shfl_xor_sync(0xffffffffu, a3, o);
        }
        if (lane == 0) {
            s_s[ti][0] = a0; s_s[ti][1] = a1; s_s[ti][2] = a2; s_s[ti][3] = a3;
        }
    }
    __syncthreads();

    // ---- softmax over positions per channel, scaled by layer weight --------
    if (tid < C_) {
        const int c = tid;
        float m = -1e30f;
        for (int i = 0; i < nt; i++) m = fmaxf(m, s_s[i][c]);
        float s = 0.f;
        for (int i = 0; i < nt; i++) { float e = expf(s_s[i][c] - m); s_s[i][c] = e; s += e; }
        float inv = s_lw / s;
        for (int i = 0; i < nt; i++) s_s[i][c] *= inv;
    }
    __syncthreads();

    for (int i = tid; i < nt * C_; i += TPB)
        g_w[mt][b][l][i / C_][i % C_] = s_s[i / C_][i % C_];
}

// ---------------------------------------------------------------------------
// Kernel 2: grid (6, 2*B_) x 128 threads; thread-per-h gather-accumulate.
// Rows are L2-resident (kernel 1 just read them). All loads in the l/i loops
// are independent -> high MLP, latency hidden across 96 blocks.
// ---------------------------------------------------------------------------
__global__ __launch_bounds__(128)
void output_kernel(const float* __restrict__ hidden,
                   float* __restrict__ out) {           // (B, 2, C, H)
    const int seg = blockIdx.x;         // 0..5
    const int bm  = blockIdx.y;         // 0..15
    const int b   = bm >> 1;
    const int mt  = bm & 1;
    const int tid = threadIdx.x;
    const int h   = seg * 128 + tid;

    __shared__ float s_w[L_][MAXNT][C_];
    __shared__ int   s_idx[MAXNT];

    const int nt = g_mask_cnt[mt][b];
    for (int i = tid; i < nt; i += 128) s_idx[i] = g_mask_idx[mt][b][i];
    for (int i = tid; i < L_ * nt * C_; i += 128) {
        int l = i / (nt * C_), r = i % (nt * C_);
        s_w[l][r / C_][r % C_] = g_w[mt][b][l][r / C_][r % C_];
    }
    __syncthreads();

    float a0 = 0.f, a1 = 0.f, a2 = 0.f, a3 = 0.f;
    #pragma unroll
    for (int l = 0; l < L_; l++) {
        const float* hb = hidden + ((size_t)(l + 1) * B_ + b) * (size_t)T_ * H_ + h;
        for (int i = 0; i < nt; i++) {
            float x = hb[(size_t)s_idx[i] * H_];
            a0 = fmaf(s_w[l][i][0], x, a0);
            a1 = fmaf(s_w[l][i][1], x, a1);
            a2 = fmaf(s_w[l][i][2], x, a2);
            a3 = fmaf(s_w[l][i][3], x, a3);
        }
    }
    float* op = out + ((size_t)b * 2 + mt) * (C_ * H_);
    op[0 * H_ + h] = a0;
    op[1 * H_ + h] = a1;
    op[2 * H_ + h] = a2;
    op[3 * H_ + h] = a3;
}

// ---------------------------------------------------------------------------
extern "C" void kernel_launch(void* const* d_in, const int* in_sizes, int n_in,
                              void* d_out, int out_size) {
    const float* hidden = (const float*)d_in[0];
    const int*   ids    = (const int*)d_in[1];
    const float* logits = (const float*)d_in[2];
    const float* scorer = (const float*)d_in[3];
    const int*   hte    = (const int*)d_in[4];   // low 4B valid for i32/i64 small values
    const int*   dtok   = (const int*)d_in[5];
    const int*   win    = (const int*)d_in[6];
    const int n_d = in_sizes[5];

    dim3 g1(L_, 2 * B_);
    scores_kernel<<<g1, TPB>>>(hidden, scorer, logits, ids, hte, win, dtok, n_d);
    dim3 g2(H_ / 128, 2 * B_);
    output_kernel<<<g2, 128>>>(hidden, (float*)d_out);
}

// round 5
// speedup vs baseline: 4.2076x; 1.4047x over previous
#include <cuda_runtime.h>

// Problem constants (fixed instance: MultiHeadAggregator_55825984913801)
#define L_    12     // layers used (hidden_states[1:])
#define B_    8
#define T_    2048
#define H_    768
#define C_    4
#define MAXNT 160    // max masked positions supported (expected: hte<=5, desc~12)
#define RCACHE 32    // rows cached in smem (fallback to global re-read beyond)
#define TPB   256
#define TOKS_PER_THR (T_ / TPB)   // 8

// Per-layer partial outputs: [L][ (2B)*C*H ], summed by finish_kernel.
__device__ float g_part[L_][2 * B_ * C_ * H_];   // 2.36 MB

// ---------------------------------------------------------------------------
// Fused kernel: one block per (b, mt, l).
//  - detects int32 vs int64 ids on device (int64 LE view of small tokens has
//    every odd 32-bit word == 0)
//  - builds the mask for (b, mt) deterministically (order-preserving scan)
//  - gathers masked rows ONCE (float4), caching them in dynamic smem
//  - computes scores -> softmax over positions -> folds in layer weight
//  - computes this layer's partial output from the smem-cached rows
// Only masked positions contribute: -1e30 masking + fp32 softmax zeroes all
// other positions exactly, so the dense reference reduces to this sparse form.
// ---------------------------------------------------------------------------
__global__ __launch_bounds__(TPB)
void scores_kernel(const float* __restrict__ hidden,      // (L_+1, B, T, H)
                   const float* __restrict__ scorer_w,    // (C, H)
                   const float* __restrict__ layer_logits,// (L_)
                   const int*   __restrict__ ids32,
                   const int*   __restrict__ hte_ptr,     // low 4B of scalar
                   const int*   __restrict__ win_ptr,     // low 4B of scalar
                   const int*   __restrict__ dtok32,
                   int n_d) {
    const int l  = blockIdx.x;          // 0..L_-1
    const int bm = blockIdx.y;          // 0..2*B_-1
    const int b  = bm >> 1;
    const int mt = bm & 1;
    const int tid  = threadIdx.x;
    const int wid  = tid >> 5, lane = tid & 31;

    extern __shared__ char dsm[];
    float4* s_sc4  = (float4*)dsm;                         // 12 KB scorer
    float*  s_rows = (float*)(dsm + C_ * (H_ / 4) * 16);   // RCACHE x 768 f32

    __shared__ float  s_s[MAXNT][C_];
    __shared__ int    s_idx[MAXNT];
    __shared__ int    s_nt;
    __shared__ int    s_notzero, s_min;
    __shared__ int    s_wsum[TPB / 32], s_woff[TPB / 32];
    __shared__ float  s_lw;

    // ---- scorer weights to smem -------------------------------------------
    {
        const float4* sw4 = (const float4*)scorer_w;
        for (int i = tid; i < C_ * (H_ / 4); i += TPB) s_sc4[i] = sw4[i];
    }

    // ---- dtype probe (parallel) + layer softmax ----------------------------
    if (tid == 0) { s_notzero = 0; s_min = 0x7fffffff; }
    __syncthreads();
    if (tid < 128 && ids32[2 * tid + 1] != 0) atomicOr(&s_notzero, 1);
    if (tid == 0) {
        float m = -1e30f;
        #pragma unroll
        for (int k = 0; k < L_; k++) m = fmaxf(m, layer_logits[k]);
        float s = 0.f, el = 0.f;
        #pragma unroll
        for (int k = 0; k < L_; k++) {
            float e = expf(layer_logits[k] - m);
            s += e;
            if (k == l) el = e;
        }
        s_lw = el / s;
    }
    __syncthreads();
    const int st  = s_notzero ? 1 : 2;
    const int hte = *hte_ptr;
    const int* row = ids32 + (size_t)b * T_ * st;

    // ---- build mask index list for (b, mt), deterministic ------------------
    if (mt == 0) {
        int local = 0x7fffffff;
        #pragma unroll
        for (int j = 0; j < TOKS_PER_THR; j++) {
            int t = tid * TOKS_PER_THR + j;
            if (row[(size_t)t * st] == hte) local = min(local, t);
        }
        if (local != 0x7fffffff) atomicMin(&s_min, local);
        __syncthreads();
        if (tid == 0) {
            int pos = (s_min == 0x7fffffff) ? (T_ - 1) : s_min;
            int hi  = pos + (*win_ptr);
            if (hi > T_ - 1) hi = T_ - 1;
            int cnt = hi - pos + 1;
            if (cnt > MAXNT) cnt = MAXNT;
            s_nt = cnt;
            for (int i = 0; i < cnt; i++) s_idx[i] = pos + i;
        }
        __syncthreads();
    } else {
        int d0 = (n_d > 0) ? dtok32[0 * st] : 0x7fffffff;
        int d1 = (n_d > 1) ? dtok32[1 * st] : 0x7fffffff;
        int d2 = (n_d > 2) ? dtok32[2 * st] : 0x7fffffff;
        int cnt = 0, loc[TOKS_PER_THR];
        #pragma unroll
        for (int j = 0; j < TOKS_PER_THR; j++) {
            int t  = tid * TOKS_PER_THR + j;
            int id = row[(size_t)t * st];
            bool isd = (id == d0) | (id == d1) | (id == d2);
            for (int k = 3; k < n_d; k++) isd |= (id == dtok32[k * st]);
            if (isd) loc[cnt++] = t;
        }
        int inc = cnt;
        #pragma unroll
        for (int o = 1; o < 32; o <<= 1) {
            int y = __shfl_up_sync(0xffffffffu, inc, o);
            if (lane >= o) inc += y;
        }
        if (lane == 31) s_wsum[wid] = inc;
        __syncthreads();
        if (tid == 0) {
            int acc = 0;
            #pragma unroll
            for (int w = 0; w < TPB / 32; w++) { s_woff[w] = acc; acc += s_wsum[w]; }
            int total = acc;
            if (total == 0) { s_idx[0] = 0; total = 1; }
            s_nt = (total > MAXNT) ? MAXNT : total;
        }
        __syncthreads();
        int off = s_woff[wid] + inc - cnt;   // exclusive prefix
        for (int k = 0; k < cnt; k++)
            if (off + k < MAXNT) s_idx[off + k] = loc[k];
        __syncthreads();
    }
    const int nt = s_nt;

    // ---- scores: warp per masked position; cache rows in smem --------------
    const float*  hbase_f = hidden + (((size_t)(l + 1) * B_ + b) * T_) * H_;
    const float4* hbase   = (const float4*)hbase_f;
    for (int ti = wid; ti < nt; ti += TPB / 32) {
        const float4* hp = hbase + (size_t)s_idx[ti] * (H_ / 4);
        float4* cache4 = (ti < RCACHE) ? (float4*)(s_rows + ti * H_) : (float4*)0;
        float a0 = 0.f, a1 = 0.f, a2 = 0.f, a3 = 0.f;
        #pragma unroll
        for (int j = 0; j < H_ / 4 / 32; j++) {        // 6 iterations
            int idx = j * 32 + lane;
            float4 x  = hp[idx];
            if (cache4) cache4[idx] = x;
            float4 w0 = s_sc4[0 * (H_ / 4) + idx];
            float4 w1 = s_sc4[1 * (H_ / 4) + idx];
            float4 w2 = s_sc4[2 * (H_ / 4) + idx];
            float4 w3 = s_sc4[3 * (H_ / 4) + idx];
            a0 = fmaf(x.x, w0.x, fmaf(x.y, w0.y, fmaf(x.z, w0.z, fmaf(x.w, w0.w, a0))));
            a1 = fmaf(x.x, w1.x, fmaf(x.y, w1.y, fmaf(x.z, w1.z, fmaf(x.w, w1.w, a1))));
            a2 = fmaf(x.x, w2.x, fmaf(x.y, w2.y, fmaf(x.z, w2.z, fmaf(x.w, w2.w, a2))));
            a3 = fmaf(x.x, w3.x, fmaf(x.y, w3.y, fmaf(x.z, w3.z, fmaf(x.w, w3.w, a3))));
        }
        #pragma unroll
        for (int o = 16; o; o >>= 1) {
            a0 += __shfl_xor_sync(0xffffffffu, a0, o);
            a1 += __shfl_xor_sync(0xffffffffu, a1, o);
            a2 += __shfl_xor_sync(0xffffffffu, a2, o);
            a3 += __shfl_xor_sync(0xffffffffu, a3, o);
        }
        if (lane == 0) {
            s_s[ti][0] = a0; s_s[ti][1] = a1; s_s[ti][2] = a2; s_s[ti][3] = a3;
        }
    }
    __syncthreads();

    // ---- softmax over positions per channel, scaled by layer weight --------
    if (tid < C_) {
        const int c = tid;
        float m = -1e30f;
        for (int i = 0; i < nt; i++) m = fmaxf(m, s_s[i][c]);
        float s = 0.f;
        for (int i = 0; i < nt; i++) { float e = expf(s_s[i][c] - m); s_s[i][c] = e; s += e; }
        float inv = s_lw / s;
        for (int i = 0; i < nt; i++) s_s[i][c] *= inv;
    }
    __syncthreads();

    // ---- this layer's partial output from smem-cached rows ------------------
    // part[c][h] = sum_i w[i][c] * row[i][h]
    float* pp = &g_part[l][(size_t)bm * C_ * H_];
    for (int h = tid; h < H_; h += TPB) {
        float a0 = 0.f, a1 = 0.f, a2 = 0.f, a3 = 0.f;
        for (int i = 0; i < nt; i++) {
            float x = (i < RCACHE) ? s_rows[i * H_ + h]
                                   : hbase_f[(size_t)s_idx[i] * H_ + h];  // L2 hit
            a0 = fmaf(s_s[i][0], x, a0);
            a1 = fmaf(s_s[i][1], x, a1);
            a2 = fmaf(s_s[i][2], x, a2);
            a3 = fmaf(s_s[i][3], x, a3);
        }
        pp[0 * H_ + h] = a0;
        pp[1 * H_ + h] = a1;
        pp[2 * H_ + h] = a2;
        pp[3 * H_ + h] = a3;
    }
}

// ---------------------------------------------------------------------------
// Finish: out[bm][c][h] = sum_l g_part[l][bm][c][h].  All reads L2-hot.
// ---------------------------------------------------------------------------
__global__ __launch_bounds__(256)
void finish_kernel(float* __restrict__ out) {
    const int idx = blockIdx.x * 256 + threadIdx.x;   // < 2B*C*H = 49152
    float s = 0.f;
    #pragma unroll
    for (int l = 0; l < L_; l++) s += g_part[l][idx];
    out[idx] = s;
}

// ---------------------------------------------------------------------------
extern "C" void kernel_launch(void* const* d_in, const int* in_sizes, int n_in,
                              void* d_out, int out_size) {
    const float* hidden = (const float*)d_in[0];
    const int*   ids    = (const int*)d_in[1];
    const float* logits = (const float*)d_in[2];
    const float* scorer = (const float*)d_in[3];
    const int*   hte    = (const int*)d_in[4];   // low 4B valid for i32/i64 small values
    const int*   dtok   = (const int*)d_in[5];
    const int*   win    = (const int*)d_in[6];
    const int n_d = in_sizes[5];

    const int dyn_smem = C_ * (H_ / 4) * 16 + RCACHE * H_ * 4;  // 12 KB + 96 KB
    cudaFuncSetAttribute(scores_kernel,
                         cudaFuncAttributeMaxDynamicSharedMemorySize, dyn_smem);

    dim3 g1(L_, 2 * B_);
    scores_kernel<<<g1, TPB, dyn_smem>>>(hidden, scorer, logits, ids,
                                         hte, win, dtok, n_d);
    finish_kernel<<<(2 * B_ * C_ * H_) / 256, 256>>>((float*)d_out);
}

// round 6
// speedup vs baseline: 4.2894x; 1.0194x over previous
#include <cuda_runtime.h>

// Problem constants (fixed instance: MultiHeadAggregator_55825984913801)
#define L_    12     // layers used (hidden_states[1:])
#define B_    8
#define T_    2048
#define H_    768
#define C_    4
#define MAXNT 160    // max masked positions supported (expected: hte<=5, desc~12)
#define RCACHE 24    // rows cached in smem (fallback to global reads beyond)
#define TPB   256
#define TOKS_PER_THR (T_ / TPB)   // 8

// Per-layer partial outputs + completion counters (zero-init; counters are
// reset by the reducing block so graph replays stay correct).
__device__ float g_part[L_][2 * B_ * C_ * H_];   // 2.36 MB
__device__ int   g_cnt[2 * B_];

// ---------------------------------------------------------------------------
// Single fused kernel: one block per (b, mt, l).
//  - dtype probe (int32 vs int64 ids) overlapped with a speculative stride-1
//    token scan (stride-1 indices are in-bounds under both hypotheses)
//  - deterministic order-preserving mask compaction for (b, mt)
//  - gathers masked rows once (float4), caching them in dynamic smem
//  - scores -> per-position softmax -> layer-softmax weight folded in
//  - layer partial output written; LAST block per bm reduces all 12 partials
//    into d_out (fixed l-order sum -> deterministic), resets the counter.
// Only masked positions contribute: -1e30 masking + fp32 softmax zeroes all
// other positions exactly, so the dense reference reduces to this sparse form.
// ---------------------------------------------------------------------------
__global__ __launch_bounds__(TPB)
void fused_kernel(const float* __restrict__ hidden,      // (L_+1, B, T, H)
                  const float* __restrict__ scorer_w,    // (C, H)
                  const float* __restrict__ layer_logits,// (L_)
                  const int*   __restrict__ ids32,
                  const int*   __restrict__ hte_ptr,     // low 4B of scalar
                  const int*   __restrict__ win_ptr,     // low 4B of scalar
                  const int*   __restrict__ dtok32,
                  int n_d,
                  float* __restrict__ out) {             // (B, 2, C, H)
    const int l  = blockIdx.x;          // 0..L_-1
    const int bm = blockIdx.y;          // 0..2*B_-1  (== b*2 + mt)
    const int b  = bm >> 1;
    const int mt = bm & 1;
    const int tid  = threadIdx.x;
    const int wid  = tid >> 5, lane = tid & 31;

    extern __shared__ char dsm[];
    float4* s_sc4  = (float4*)dsm;                         // 12 KB scorer
    float*  s_rows = (float*)(dsm + C_ * (H_ / 4) * 16);   // RCACHE x 768 f32

    __shared__ float  s_s[MAXNT][C_];
    __shared__ int    s_idx[MAXNT];
    __shared__ int    s_nt;
    __shared__ int    s_notzero, s_min;
    __shared__ int    s_wsum[TPB / 32], s_woff[TPB / 32];
    __shared__ float  s_lw;
    __shared__ int    s_last;

    // ---- scorer weights to smem (in flight with the scans below) ----------
    {
        const float4* sw4 = (const float4*)scorer_w;
        for (int i = tid; i < C_ * (H_ / 4); i += TPB) s_sc4[i] = sw4[i];
    }

    if (tid == 0) { s_notzero = 0; s_min = 0x7fffffff; }
    __syncthreads();

    // ---- probe + SPECULATIVE stride-1 token scan (same latency epoch) -----
    // stride-1 indices b*T + t are in-bounds whether the buffer is int32
    // (B*T words) or int64 (2*B*T words).
    int myids[TOKS_PER_THR];
    {
        const int* row1 = ids32 + (size_t)b * T_;
        #pragma unroll
        for (int j = 0; j < TOKS_PER_THR; j++)
            myids[j] = row1[tid * TOKS_PER_THR + j];
    }
    if (tid < 128 && ids32[2 * tid + 1] != 0) atomicOr(&s_notzero, 1);
    if (tid == 0) {   // layer softmax (12 elems, cheap)
        float m = -1e30f;
        #pragma unroll
        for (int k = 0; k < L_; k++) m = fmaxf(m, layer_logits[k]);
        float s = 0.f, el = 0.f;
        #pragma unroll
        for (int k = 0; k < L_; k++) {
            float e = expf(layer_logits[k] - m);
            s += e;
            if (k == l) el = e;
        }
        s_lw = el / s;
    }
    __syncthreads();
    const int st = s_notzero ? 1 : 2;
    if (st == 2) {  // rare path: buffer was int64 -> re-load at stride 2
        const int* row2 = ids32 + (size_t)b * T_ * 2;
        #pragma unroll
        for (int j = 0; j < TOKS_PER_THR; j++)
            myids[j] = row2[(size_t)(tid * TOKS_PER_THR + j) * 2];
    }
    const int hte = *hte_ptr;

    // ---- build mask index list for (b, mt), deterministic ------------------
    if (mt == 0) {
        int local = 0x7fffffff;
        #pragma unroll
        for (int j = 0; j < TOKS_PER_THR; j++)
            if (myids[j] == hte) local = min(local, tid * TOKS_PER_THR + j);
        if (local != 0x7fffffff) atomicMin(&s_min, local);
        __syncthreads();
        if (tid == 0) {
            int pos = (s_min == 0x7fffffff) ? (T_ - 1) : s_min;
            int hi  = pos + (*win_ptr);
            if (hi > T_ - 1) hi = T_ - 1;
            int cnt = hi - pos + 1;
            if (cnt > MAXNT) cnt = MAXNT;
            s_nt = cnt;
            for (int i = 0; i < cnt; i++) s_idx[i] = pos + i;
        }
        __syncthreads();
    } else {
        int d0 = (n_d > 0) ? dtok32[0 * st] : 0x7fffffff;
        int d1 = (n_d > 1) ? dtok32[1 * st] : 0x7fffffff;
        int d2 = (n_d > 2) ? dtok32[2 * st] : 0x7fffffff;
        int cnt = 0, loc[TOKS_PER_THR];
        #pragma unroll
        for (int j = 0; j < TOKS_PER_THR; j++) {
            int id = myids[j];
            bool isd = (id == d0) | (id == d1) | (id == d2);
            for (int k = 3; k < n_d; k++) isd |= (id == dtok32[k * st]);
            if (isd) loc[cnt++] = tid * TOKS_PER_THR + j;
        }
        int inc = cnt;
        #pragma unroll
        for (int o = 1; o < 32; o <<= 1) {
            int y = __shfl_up_sync(0xffffffffu, inc, o);
            if (lane >= o) inc += y;
        }
        if (lane == 31) s_wsum[wid] = inc;
        __syncthreads();
        if (tid == 0) {
            int acc = 0;
            #pragma unroll
            for (int w = 0; w < TPB / 32; w++) { s_woff[w] = acc; acc += s_wsum[w]; }
            int total = acc;
            if (total == 0) { s_idx[0] = 0; total = 1; }
            s_nt = (total > MAXNT) ? MAXNT : total;
        }
        __syncthreads();
        int off = s_woff[wid] + inc - cnt;   // exclusive prefix
        for (int k = 0; k < cnt; k++)
            if (off + k < MAXNT) s_idx[off + k] = loc[k];
        __syncthreads();
    }
    const int nt = s_nt;

    // ---- scores: warp per masked position; cache rows in smem --------------
    const float*  hbase_f = hidden + (((size_t)(l + 1) * B_ + b) * T_) * H_;
    const float4* hbase   = (const float4*)hbase_f;
    for (int ti = wid; ti < nt; ti += TPB / 32) {
        const float4* hp = hbase + (size_t)s_idx[ti] * (H_ / 4);
        float4* cache4 = (ti < RCACHE) ? (float4*)(s_rows + ti * H_) : (float4*)0;
        float a0 = 0.f, a1 = 0.f, a2 = 0.f, a3 = 0.f;
        #pragma unroll
        for (int j = 0; j < H_ / 4 / 32; j++) {        // 6 iterations
            int idx = j * 32 + lane;
            float4 x  = hp[idx];
            if (cache4) cache4[idx] = x;
            float4 w0 = s_sc4[0 * (H_ / 4) + idx];
            float4 w1 = s_sc4[1 * (H_ / 4) + idx];
            float4 w2 = s_sc4[2 * (H_ / 4) + idx];
            float4 w3 = s_sc4[3 * (H_ / 4) + idx];
            a0 = fmaf(x.x, w0.x, fmaf(x.y, w0.y, fmaf(x.z, w0.z, fmaf(x.w, w0.w, a0))));
            a1 = fmaf(x.x, w1.x, fmaf(x.y, w1.y, fmaf(x.z, w1.z, fmaf(x.w, w1.w, a1))));
            a2 = fmaf(x.x, w2.x, fmaf(x.y, w2.y, fmaf(x.z, w2.z, fmaf(x.w, w2.w, a2))));
            a3 = fmaf(x.x, w3.x, fmaf(x.y, w3.y, fmaf(x.z, w3.z, fmaf(x.w, w3.w, a3))));
        }
        #pragma unroll
        for (int o = 16; o; o >>= 1) {
            a0 += __shfl_xor_sync(0xffffffffu, a0, o);
            a1 += __shfl_xor_sync(0xffffffffu, a1, o);
            a2 += __shfl_xor_sync(0xffffffffu, a2, o);
            a3 += __shfl_xor_sync(0xffffffffu, a3, o);
        }
        if (lane == 0) {
            s_s[ti][0] = a0; s_s[ti][1] = a1; s_s[ti][2] = a2; s_s[ti][3] = a3;
        }
    }
    __syncthreads();

    // ---- softmax over positions per channel, scaled by layer weight --------
    if (tid < C_) {
        const int c = tid;
        float m = -1e30f;
        for (int i = 0; i < nt; i++) m = fmaxf(m, s_s[i][c]);
        float s = 0.f;
        for (int i = 0; i < nt; i++) { float e = expf(s_s[i][c] - m); s_s[i][c] = e; s += e; }
        float inv = s_lw / s;
        for (int i = 0; i < nt; i++) s_s[i][c] *= inv;
    }
    __syncthreads();

    // ---- this layer's partial output (float4) -------------------------------
    float* pp = &g_part[l][(size_t)bm * C_ * H_];
    if (tid < H_ / 4) {                     // 192 threads, one float4 each
        const int h0 = tid * 4;
        float4 a0 = {0,0,0,0}, a1 = {0,0,0,0}, a2 = {0,0,0,0}, a3 = {0,0,0,0};
        for (int i = 0; i < nt; i++) {
            float4 x = (i < RCACHE) ? *(const float4*)&s_rows[i * H_ + h0]
                                    : *(const float4*)&hbase_f[(size_t)s_idx[i] * H_ + h0];
            float w0 = s_s[i][0], w1 = s_s[i][1], w2 = s_s[i][2], w3 = s_s[i][3];
            a0.x = fmaf(w0, x.x, a0.x); a0.y = fmaf(w0, x.y, a0.y); a0.z = fmaf(w0, x.z, a0.z); a0.w = fmaf(w0, x.w, a0.w);
            a1.x = fmaf(w1, x.x, a1.x); a1.y = fmaf(w1, x.y, a1.y); a1.z = fmaf(w1, x.z, a1.z); a1.w = fmaf(w1, x.w, a1.w);
            a2.x = fmaf(w2, x.x, a2.x); a2.y = fmaf(w2, x.y, a2.y); a2.z = fmaf(w2, x.z, a2.z); a2.w = fmaf(w2, x.w, a2.w);
            a3.x = fmaf(w3, x.x, a3.x); a3.y = fmaf(w3, x.y, a3.y); a3.z = fmaf(w3, x.z, a3.z); a3.w = fmaf(w3, x.w, a3.w);
        }
        *(float4*)&pp[0 * H_ + h0] = a0;
        *(float4*)&pp[1 * H_ + h0] = a1;
        *(float4*)&pp[2 * H_ + h0] = a2;
        *(float4*)&pp[3 * H_ + h0] = a3;
    }

    // ---- completion protocol: last block of this bm reduces into out -------
    __threadfence();                        // make partial writes visible device-wide
    __syncthreads();
    if (tid == 0) {
        int old = atomicAdd(&g_cnt[bm], 1);
        s_last = (old == L_ - 1);
    }
    __syncthreads();
    if (s_last) {
        __threadfence();                    // acquire side
        float* op = out + (size_t)bm * (C_ * H_);
        const int n4 = C_ * H_ / 4;         // 768 float4
        for (int e = tid; e < n4; e += TPB) {
            float4 s = {0,0,0,0};
            #pragma unroll
            for (int k = 0; k < L_; k++) {
                float4 v = *(const float4*)&g_part[k][(size_t)bm * C_ * H_ + e * 4];
                s.x += v.x; s.y += v.y; s.z += v.z; s.w += v.w;
            }
            ((float4*)op)[e] = s;
        }
        if (tid == 0) g_cnt[bm] = 0;        // reset for next graph replay
    }
}

// ---------------------------------------------------------------------------
extern "C" void kernel_launch(void* const* d_in, const int* in_sizes, int n_in,
                              void* d_out, int out_size) {
    const float* hidden = (const float*)d_in[0];
    const int*   ids    = (const int*)d_in[1];
    const float* logits = (const float*)d_in[2];
    const float* scorer = (const float*)d_in[3];
    const int*   hte    = (const int*)d_in[4];   // low 4B valid for i32/i64 small values
    const int*   dtok   = (const int*)d_in[5];
    const int*   win    = (const int*)d_in[6];
    const int n_d = in_sizes[5];

    const int dyn_smem = C_ * (H_ / 4) * 16 + RCACHE * H_ * 4;  // 12 KB + 72 KB
    cudaFuncSetAttribute(fused_kernel,
                         cudaFuncAttributeMaxDynamicSharedMemorySize, dyn_smem);

    dim3 g(L_, 2 * B_);
    fused_kernel<<<g, TPB, dyn_smem>>>(hidden, scorer, logits, ids,
                                       hte, win, dtok, n_d, (float*)d_out);
}